// round 8
// baseline (speedup 1.0000x reference)
#include <cuda_runtime.h>

#define NUM_LEVELS 16
#define TABLE_SZ   16384
#define CHUNKS     9
#define THREADS    1024
#define MAX_B      262144

// floor(16 * 1.38^l) computed in double precision, exactly representable in f32
__constant__ float c_res[NUM_LEVELS] = {
    16.f, 22.f, 30.f, 42.f, 58.f, 80.f, 110.f, 152.f,
    210.f, 290.f, 400.f, 553.f, 763.f, 1053.f, 1453.f, 2005.f
};

// Scratch (allocation-free rule: __device__ globals)
__device__ float2 g_scr[NUM_LEVELS * MAX_B];         // [level][b] features (33.5 MB)

extern __shared__ float2 s_tab[];  // 16384 float2 = 128 KB

// ---------------------------------------------------------------- main
__device__ __forceinline__ void hash_point(const float px, const float py,
                                           const float pz, const float res,
                                           float& ox, float& oy)
{
    // Interpolation weights use the UNSCALED position (faithful to source)
    const float wx = px - floorf(px);
    const float wy = py - floorf(py);
    const float wz = pz - floorf(pz);

    const float sx = res * px;
    const float sy = res * py;
    const float sz = res * pz;

    const int lx = __float2int_rd(sx);
    const int ly = __float2int_rd(sy);
    const int lz = __float2int_rd(sz);
    const int hx = __float2int_ru(sx);
    const int hy = __float2int_ru(sy);
    const int hz = __float2int_ru(sz);

    // int32 wraparound multiply == uint32 multiply (same bits);
    // python remainder by 16384 == & 16383 on two's complement
    const unsigned ay0 = 2654435761u * (unsigned)ly;
    const unsigned ay1 = 2654435761u * (unsigned)hy;
    const unsigned az0 = 805459861u  * (unsigned)lz;
    const unsigned az1 = 805459861u  * (unsigned)hz;

    const unsigned b00 = ay0 ^ az0;
    const unsigned b10 = ay1 ^ az0;
    const unsigned b01 = ay0 ^ az1;
    const unsigned b11 = ay1 ^ az1;
    const unsigned ux = (unsigned)lx;
    const unsigned vx = (unsigned)hx;

    // Corner order v0..v7: (0,0,0)(1,0,0)(1,1,0)(0,1,0)(0,0,1)(1,0,1)(1,1,1)(0,1,1)
    const float2 f0 = s_tab[(ux ^ b00) & 16383u];
    const float2 f1 = s_tab[(vx ^ b00) & 16383u];
    const float2 f2 = s_tab[(vx ^ b10) & 16383u];
    const float2 f3 = s_tab[(ux ^ b10) & 16383u];
    const float2 f4 = s_tab[(ux ^ b01) & 16383u];
    const float2 f5 = s_tab[(vx ^ b01) & 16383u];
    const float2 f6 = s_tab[(vx ^ b11) & 16383u];
    const float2 f7 = s_tab[(ux ^ b11) & 16383u];

    const float ex = 1.f - wx, ey = 1.f - wy, ez = 1.f - wz;
    const float w00 = ex * ey, w10 = wx * ey, w11 = wx * wy, w01 = ex * wy;
    const float c0 = w00 * ez, c1 = w10 * ez, c2 = w11 * ez, c3 = w01 * ez;
    const float c4 = w00 * wz, c5 = w10 * wz, c6 = w11 * wz, c7 = w01 * wz;

    float vxr = c0 * f0.x;
    vxr = fmaf(c1, f1.x, vxr);
    vxr = fmaf(c2, f2.x, vxr);
    vxr = fmaf(c3, f3.x, vxr);
    vxr = fmaf(c4, f4.x, vxr);
    vxr = fmaf(c5, f5.x, vxr);
    vxr = fmaf(c6, f6.x, vxr);
    vxr = fmaf(c7, f7.x, vxr);

    float vyr = c0 * f0.y;
    vyr = fmaf(c1, f1.y, vyr);
    vyr = fmaf(c2, f2.y, vyr);
    vyr = fmaf(c3, f3.y, vyr);
    vyr = fmaf(c4, f4.y, vyr);
    vyr = fmaf(c5, f5.y, vyr);
    vyr = fmaf(c6, f6.y, vyr);
    vyr = fmaf(c7, f7.y, vyr);

    ox = vxr;
    oy = vyr;
}

__global__ __launch_bounds__(THREADS, 1)
void hashenc_kernel(const float* __restrict__ x,
                    const float* __restrict__ tables, int B)
{
    const int level = blockIdx.y;

    // Cooperative fill of this level's table into shared memory (16B chunks)
    {
        const float4* src = reinterpret_cast<const float4*>(
            tables + (size_t)level * TABLE_SZ * 2);
        float4* dst = reinterpret_cast<float4*>(s_tab);
        #pragma unroll 4
        for (int i = threadIdx.x; i < TABLE_SZ / 2; i += THREADS)
            dst[i] = src[i];
    }
    __syncthreads();

    const float res = c_res[level];
    const int per   = (B + gridDim.x - 1) / gridDim.x;  // 29128 (even)
    const int start = blockIdx.x * per;
    const int end   = min(start + per, B);

    float2* __restrict__ scr = g_scr + (size_t)level * B;
    const float2* __restrict__ x2 = reinterpret_cast<const float2*>(x);

    // Two consecutive points per thread; pairs never straddle chunk bounds.
    // 6 floats = 3 contiguous LDG.64 per thread (x is L2-resident, 3 MB).
    for (int b = start + 2 * (int)threadIdx.x; b + 1 < end; b += 2 * THREADS) {
        const float2 q0 = x2[3 * (b >> 1) + 0];   // p0.x p0.y
        const float2 q1 = x2[3 * (b >> 1) + 1];   // p0.z p1.x
        const float2 q2 = x2[3 * (b >> 1) + 2];   // p1.y p1.z

        float ox0, oy0, ox1, oy1;
        hash_point(q0.x, q0.y, q1.x, res, ox0, oy0);
        hash_point(q1.y, q2.x, q2.y, res, ox1, oy1);

        // One coalesced STG.128 for the pair (b even -> 16B aligned)
        reinterpret_cast<float4*>(scr + b)[0] = make_float4(ox0, oy0, ox1, oy1);
    }
}

// ---------------------------------------------------------------- transpose
// Block: 512 threads, tile = 256 points x 16 levels.
__global__ __launch_bounds__(512)
void transpose_kernel(float4* __restrict__ out4, int B)
{
    __shared__ float2 s[NUM_LEVELS][257];  // pad to break bank alignment
    const int b0 = blockIdx.x * 256;
    const int t  = threadIdx.x;

    #pragma unroll
    for (int i = 0; i < 8; i++) {          // 16*256 / 512 = 8
        int idx = i * 512 + t;
        int l = idx >> 8;                  // 0..15
        int p = idx & 255;
        s[l][p] = g_scr[(size_t)l * B + b0 + p];
    }
    __syncthreads();

    // 256 points * 8 float4 = 2048 outputs, 4 per thread, coalesced
    #pragma unroll
    for (int i = 0; i < 4; i++) {
        int o  = i * 512 + t;              // 0..2047
        int p  = o >> 3;
        int j  = o & 7;
        float2 a = s[2 * j + 0][p];
        float2 c = s[2 * j + 1][p];
        out4[(size_t)b0 * 8 + o] = make_float4(a.x, a.y, c.x, c.y);
    }
}

extern "C" void kernel_launch(void* const* d_in, const int* in_sizes, int n_in,
                              void* d_out, int out_size)
{
    const float* x      = (const float*)d_in[0];
    const float* tables = (const float*)d_in[1];
    float4* out4        = (float4*)d_out;
    const int B = in_sizes[0] / 3;

    const int smem = TABLE_SZ * 2 * (int)sizeof(float);  // 131072 B
    cudaFuncSetAttribute(hashenc_kernel,
                         cudaFuncAttributeMaxDynamicSharedMemorySize, smem);

    dim3 grid(CHUNKS, NUM_LEVELS);
    hashenc_kernel<<<grid, THREADS, smem>>>(x, tables, B);

    transpose_kernel<<<(B + 255) / 256, 512>>>(out4, B);
}

// round 9
// speedup vs baseline: 1.5260x; 1.5260x over previous
#include <cuda_runtime.h>

#define NUM_LEVELS 16
#define TABLE_SZ   16384
#define CHUNKS     9
#define THREADS    1024
#define MAX_B      262144

// floor(16 * 1.38^l) computed in double precision, exactly representable in f32
__constant__ float c_res[NUM_LEVELS] = {
    16.f, 22.f, 30.f, 42.f, 58.f, 80.f, 110.f, 152.f,
    210.f, 290.f, 400.f, 553.f, 763.f, 1053.f, 1453.f, 2005.f
};

// Scratch (allocation-free rule: __device__ globals)
__device__ float4 g_xs[MAX_B];                       // packed positions (4 MB)
__device__ float2 g_scr[NUM_LEVELS * MAX_B];         // [level][b] features (33.5 MB)

extern __shared__ float2 s_tab[];  // main: 16384 float2 = 128 KB

// ---------------------------------------------------------------- pack x
__global__ __launch_bounds__(256)
void pack_x_kernel(const float4* __restrict__ x4, int B)
{
    __shared__ float sx[256 * 3];
    const int b0 = blockIdx.x * 256;
    const int t  = threadIdx.x;
    if (t < 192) {
        float4 v = x4[(size_t)(b0 * 3) / 4 + t];
        sx[4 * t + 0] = v.x; sx[4 * t + 1] = v.y;
        sx[4 * t + 2] = v.z; sx[4 * t + 3] = v.w;
    }
    __syncthreads();
    const int b = b0 + t;
    if (b < B)
        g_xs[b] = make_float4(sx[3 * t], sx[3 * t + 1], sx[3 * t + 2], 0.f);
}

// ---------------------------------------------------------------- main
__device__ __forceinline__ void hash_point(const float px, const float py,
                                           const float pz, const float res,
                                           float& ox, float& oy)
{
    // Interpolation weights use the UNSCALED position (faithful to source)
    const float wx = px - floorf(px);
    const float wy = py - floorf(py);
    const float wz = pz - floorf(pz);

    const float sx = res * px;
    const float sy = res * py;
    const float sz = res * pz;

    const int lx = __float2int_rd(sx);
    const int ly = __float2int_rd(sy);
    const int lz = __float2int_rd(sz);
    const int hx = __float2int_ru(sx);
    const int hy = __float2int_ru(sy);
    const int hz = __float2int_ru(sz);

    // int32 wraparound multiply == uint32 multiply (same bits);
    // python remainder by 16384 == & 16383 on two's complement
    const unsigned ay0 = 2654435761u * (unsigned)ly;
    const unsigned ay1 = 2654435761u * (unsigned)hy;
    const unsigned az0 = 805459861u  * (unsigned)lz;
    const unsigned az1 = 805459861u  * (unsigned)hz;

    const unsigned b00 = ay0 ^ az0;
    const unsigned b10 = ay1 ^ az0;
    const unsigned b01 = ay0 ^ az1;
    const unsigned b11 = ay1 ^ az1;
    const unsigned ux = (unsigned)lx;
    const unsigned vx = (unsigned)hx;

    // Corner order v0..v7: (0,0,0)(1,0,0)(1,1,0)(0,1,0)(0,0,1)(1,0,1)(1,1,1)(0,1,1)
    const float2 f0 = s_tab[(ux ^ b00) & 16383u];
    const float2 f1 = s_tab[(vx ^ b00) & 16383u];
    const float2 f2 = s_tab[(vx ^ b10) & 16383u];
    const float2 f3 = s_tab[(ux ^ b10) & 16383u];
    const float2 f4 = s_tab[(ux ^ b01) & 16383u];
    const float2 f5 = s_tab[(vx ^ b01) & 16383u];
    const float2 f6 = s_tab[(vx ^ b11) & 16383u];
    const float2 f7 = s_tab[(ux ^ b11) & 16383u];

    const float ex = 1.f - wx, ey = 1.f - wy, ez = 1.f - wz;
    const float w00 = ex * ey, w10 = wx * ey, w11 = wx * wy, w01 = ex * wy;
    const float c0 = w00 * ez, c1 = w10 * ez, c2 = w11 * ez, c3 = w01 * ez;
    const float c4 = w00 * wz, c5 = w10 * wz, c6 = w11 * wz, c7 = w01 * wz;

    float vxr = c0 * f0.x;
    vxr = fmaf(c1, f1.x, vxr);
    vxr = fmaf(c2, f2.x, vxr);
    vxr = fmaf(c3, f3.x, vxr);
    vxr = fmaf(c4, f4.x, vxr);
    vxr = fmaf(c5, f5.x, vxr);
    vxr = fmaf(c6, f6.x, vxr);
    vxr = fmaf(c7, f7.x, vxr);

    float vyr = c0 * f0.y;
    vyr = fmaf(c1, f1.y, vyr);
    vyr = fmaf(c2, f2.y, vyr);
    vyr = fmaf(c3, f3.y, vyr);
    vyr = fmaf(c4, f4.y, vyr);
    vyr = fmaf(c5, f5.y, vyr);
    vyr = fmaf(c6, f6.y, vyr);
    vyr = fmaf(c7, f7.y, vyr);

    ox = vxr;
    oy = vyr;
}

__global__ __launch_bounds__(THREADS, 1)
void hashenc_kernel(const float* __restrict__ tables, int B)
{
    const int level = blockIdx.y;

    // Cooperative fill of this level's table into shared memory (16B chunks)
    {
        const float4* src = reinterpret_cast<const float4*>(
            tables + (size_t)level * TABLE_SZ * 2);
        float4* dst = reinterpret_cast<float4*>(s_tab);
        #pragma unroll 4
        for (int i = threadIdx.x; i < TABLE_SZ / 2; i += THREADS)
            dst[i] = src[i];
    }
    __syncthreads();

    const float res = c_res[level];
    const int per   = (B + gridDim.x - 1) / gridDim.x;  // 29128 (even)
    const int start = blockIdx.x * per;
    const int end   = min(start + per, B);

    float2* __restrict__ scr = g_scr + (size_t)level * B;

    // Two consecutive points per thread; pairs never straddle chunk bounds
    for (int b = start + 2 * (int)threadIdx.x; b + 1 < end; b += 2 * THREADS) {
        const float4 p0 = g_xs[b];
        const float4 p1 = g_xs[b + 1];

        float ox0, oy0, ox1, oy1;
        hash_point(p0.x, p0.y, p0.z, res, ox0, oy0);
        hash_point(p1.x, p1.y, p1.z, res, ox1, oy1);

        // One coalesced STG.128 for the pair (b even -> 16B aligned)
        reinterpret_cast<float4*>(scr + b)[0] = make_float4(ox0, oy0, ox1, oy1);
    }
}

// ---------------------------------------------------------------- transpose
// Tile: 512 points x 16 levels, 1024 threads, 64 KB dynamic smem.
// Phase 1: float4 loads of g_scr rows (2 points/load), conflict-free STS.128.
// Phase 2: coalesced STG.128 to out, ~2-way-conflict LDS.64 reads.
#define TP_PTS   512
#define TP_ROW4  257   // 256 float4 per row + 1 pad  (514 float2)

extern __shared__ float4 s4[];   // [16][TP_ROW4]

__global__ __launch_bounds__(1024)
void transpose_kernel(float4* __restrict__ out4, int B)
{
    const int b0 = blockIdx.x * TP_PTS;
    const int t  = threadIdx.x;
    const float4* __restrict__ g4 = reinterpret_cast<const float4*>(g_scr);
    const int halfB = B >> 1;

    // Phase 1: 16 rows * 256 float4 = 4096 loads / 1024 thr = 4 per thread
    #pragma unroll
    for (int i = 0; i < 4; i++) {
        int idx = i * 1024 + t;            // 0..4095
        int l = idx >> 8;                  // 0..15
        int q = idx & 255;                 // pair index 0..255
        s4[l * TP_ROW4 + q] = g4[(size_t)l * halfB + (b0 >> 1) + q];
    }
    __syncthreads();

    // Phase 2: 512 points * 8 float4 = 4096 outputs / 1024 thr = 4 per thread
    const float2* __restrict__ s2 = reinterpret_cast<const float2*>(s4);
    #pragma unroll
    for (int i = 0; i < 4; i++) {
        int o = i * 1024 + t;              // 0..4095
        int p = o >> 3;                    // point 0..511
        int j = o & 7;                     // level-pair 0..7
        float2 a = s2[(2 * j + 0) * (2 * TP_ROW4) + p];
        float2 c = s2[(2 * j + 1) * (2 * TP_ROW4) + p];
        out4[(size_t)b0 * 8 + o] = make_float4(a.x, a.y, c.x, c.y);
    }
}

extern "C" void kernel_launch(void* const* d_in, const int* in_sizes, int n_in,
                              void* d_out, int out_size)
{
    const float* x      = (const float*)d_in[0];
    const float* tables = (const float*)d_in[1];
    float4* out4        = (float4*)d_out;
    const int B = in_sizes[0] / 3;

    const int smem_main = TABLE_SZ * 2 * (int)sizeof(float);       // 131072 B
    cudaFuncSetAttribute(hashenc_kernel,
                         cudaFuncAttributeMaxDynamicSharedMemorySize, smem_main);

    const int smem_tp = NUM_LEVELS * TP_ROW4 * (int)sizeof(float4); // 65792 B
    cudaFuncSetAttribute(transpose_kernel,
                         cudaFuncAttributeMaxDynamicSharedMemorySize, smem_tp);

    pack_x_kernel<<<(B + 255) / 256, 256>>>((const float4*)x, B);

    dim3 grid(CHUNKS, NUM_LEVELS);
    hashenc_kernel<<<grid, THREADS, smem_main>>>(tables, B);

    transpose_kernel<<<(B + TP_PTS - 1) / TP_PTS, 1024, smem_tp>>>(out4, B);
}